// round 1
// baseline (speedup 1.0000x reference)
#include <cuda_runtime.h>
#include <math.h>

#define BB 8
#define CCH 256
#define HH 112
#define WWI 112
#define HW 12544
#define CHW 3211264      // CCH*HW
#define PP 196
#define TG 56
#define AA 3136          // TG*TG
#define CA 802816        // CCH*AA
#define PSCALE 0.0078125f   // (C*S)^-0.5 = 1/128
#define GSCALE 0.0625f      // C^-0.5 = 1/16

// ---------------- scratch (device globals; no allocations allowed) ----------
__device__ float g_xn[BB*CHW];
__device__ float g_q [BB*CHW];
__device__ float g_k [BB*CHW];
__device__ float g_v [BB*CHW];
__device__ float g_h [BB*CHW];
__device__ float g_qp[BB*CA];
__device__ float g_kp[BB*CA];
__device__ float g_vp[BB*CA];
__device__ float g_hg[BB*CA];
__device__ float g_attp[BB*PP*PP];
__device__ float g_attg[78675968];   // BB*AA*AA
__device__ double g_sum[BB], g_sq[BB];
__device__ float g_mean[BB], g_rstd[BB];

__device__ __forceinline__ void fma16(float (&acc)[4][4], float4 a, float4 b) {
    acc[0][0] += a.x*b.x; acc[0][1] += a.x*b.y; acc[0][2] += a.x*b.z; acc[0][3] += a.x*b.w;
    acc[1][0] += a.y*b.x; acc[1][1] += a.y*b.y; acc[1][2] += a.y*b.z; acc[1][3] += a.y*b.w;
    acc[2][0] += a.z*b.x; acc[2][1] += a.z*b.y; acc[2][2] += a.z*b.z; acc[2][3] += a.z*b.w;
    acc[3][0] += a.w*b.x; acc[3][1] += a.w*b.y; acc[3][2] += a.w*b.z; acc[3][3] += a.w*b.w;
}

// ---------------- zero scratch that is accumulated into ---------------------
__global__ void k_zero_small() {
    int t = blockIdx.x*blockDim.x + threadIdx.x;
    if (t < BB) { g_sum[t] = 0.0; g_sq[t] = 0.0; }
    for (int i = t; i < BB*PP*PP; i += gridDim.x*blockDim.x) g_attp[i] = 0.f;
}

// ---------------- GroupNorm(1) statistics -----------------------------------
__global__ void k_gnstats(const float* __restrict__ x) {
    int b = blockIdx.y;
    const float4* xb = (const float4*)(x + (size_t)b*CHW);
    const int n4 = CHW/4;
    float s = 0.f, ss = 0.f;
    for (int i = blockIdx.x*blockDim.x + threadIdx.x; i < n4; i += gridDim.x*blockDim.x) {
        float4 v = xb[i];
        s  += v.x + v.y + v.z + v.w;
        ss += v.x*v.x + v.y*v.y + v.z*v.z + v.w*v.w;
    }
    __shared__ double sh[256], sh2[256];
    sh[threadIdx.x] = (double)s; sh2[threadIdx.x] = (double)ss;
    __syncthreads();
    for (int o = 128; o > 0; o >>= 1) {
        if (threadIdx.x < o) { sh[threadIdx.x] += sh[threadIdx.x+o]; sh2[threadIdx.x] += sh2[threadIdx.x+o]; }
        __syncthreads();
    }
    if (threadIdx.x == 0) { atomicAdd(&g_sum[b], sh[0]); atomicAdd(&g_sq[b], sh2[0]); }
}

__global__ void k_gnfin() {
    int b = threadIdx.x;
    if (b < BB) {
        double n = (double)CHW;
        double mu = g_sum[b] / n;
        double var = g_sq[b] / n - mu*mu;
        g_mean[b] = (float)mu;
        g_rstd[b] = (float)rsqrt(var + 1e-5);
    }
}

// ---------------- normalize: xn = (x-mu)*rstd*gw + gb ------------------------
__global__ void k_norm(const float* __restrict__ x, const float* __restrict__ gw,
                       const float* __restrict__ gb) {
    int bc = blockIdx.x;                  // b*256 + c
    int b = bc >> 8, c = bc & 255;
    float sc = g_rstd[b] * gw[c];
    float sh = gb[c] - g_mean[b] * sc;
    const float4* src = (const float4*)(x + (size_t)bc*HW);
    float4* dst = (float4*)(g_xn + (size_t)bc*HW);
    for (int i = threadIdx.x; i < HW/4; i += blockDim.x) {
        float4 v = src[i];
        v.x = v.x*sc + sh; v.y = v.y*sc + sh; v.z = v.z*sc + sh; v.w = v.w*sc + sh;
        dst[i] = v;
    }
}

// ---------------- QKV: [768,256] @ xn[256,12544] + bias ----------------------
__global__ void __launch_bounds__(256) k_qkv(
        const float* __restrict__ wq, const float* __restrict__ bq,
        const float* __restrict__ wk, const float* __restrict__ bk,
        const float* __restrict__ wv, const float* __restrict__ bv) {
    __shared__ float As[16][68], Bs[16][68];
    int b = blockIdx.z;
    int n0 = blockIdx.x * 64;
    int oy = blockIdx.y;                  // 0..11
    int seg = oy >> 2;
    int m0 = (oy & 3) * 64;
    const float* W  = seg == 0 ? wq : (seg == 1 ? wk : wv);
    const float* Bi = seg == 0 ? bq : (seg == 1 ? bk : bv);
    float* O = (seg == 0 ? g_q : (seg == 1 ? g_k : g_v)) + (size_t)b*CHW;
    const float* X = g_xn + (size_t)b*CHW;
    int tid = threadIdx.x;
    int tx = tid & 15, ty = tid >> 4;
    int lm = tid & 63, lk4 = (tid >> 6) << 2;
    int lbk = tid >> 4, lbn = (tid & 15) << 2;
    float acc[4][4] = {};
    for (int k0 = 0; k0 < 256; k0 += 16) {
        float4 a = *(const float4*)&W[(m0+lm)*256 + k0 + lk4];
        As[lk4+0][lm] = a.x; As[lk4+1][lm] = a.y; As[lk4+2][lm] = a.z; As[lk4+3][lm] = a.w;
        *(float4*)&Bs[lbk][lbn] = *(const float4*)&X[(size_t)(k0+lbk)*HW + n0 + lbn];
        __syncthreads();
        #pragma unroll
        for (int k = 0; k < 16; k++)
            fma16(acc, *(float4*)&As[k][ty*4], *(float4*)&Bs[k][tx*4]);
        __syncthreads();
    }
    #pragma unroll
    for (int i = 0; i < 4; i++) {
        int o = m0 + ty*4 + i;
        float bias = Bi[o];
        float4 r = make_float4(acc[i][0]+bias, acc[i][1]+bias, acc[i][2]+bias, acc[i][3]+bias);
        *(float4*)&O[(size_t)o*HW + n0 + tx*4] = r;
    }
}

// ---------------- patch scores: att[p,q] += scale * sum_d Q[d,p]K[d,q] -------
__global__ void __launch_bounds__(256) k_pscore() {
    __shared__ float As[16][68], Bs[16][68];
    int bz = blockIdx.z;
    int b = bz >> 4, ks = bz & 15;        // 16-way split-K
    int m0 = blockIdx.y * 64, n0 = blockIdx.x * 64;
    const float* Q = g_q + (size_t)b*CHW;  // [16384, 196] row-major
    const float* K = g_k + (size_t)b*CHW;
    int tid = threadIdx.x;
    int tx = tid & 15, ty = tid >> 4;
    int lk = tid >> 4, ln = (tid & 15) << 2;
    float acc[4][4] = {};
    const float4 z4 = make_float4(0,0,0,0);
    int kbeg = ks * 1024, kend = kbeg + 1024;
    for (int k0 = kbeg; k0 < kend; k0 += 16) {
        int cm = m0 + ln, cn = n0 + ln;
        float4 a = (cm < PP) ? *(const float4*)&Q[(size_t)(k0+lk)*PP + cm] : z4;
        float4 bv = (cn < PP) ? *(const float4*)&K[(size_t)(k0+lk)*PP + cn] : z4;
        *(float4*)&As[lk][ln] = a;
        *(float4*)&Bs[lk][ln] = bv;
        __syncthreads();
        #pragma unroll
        for (int k = 0; k < 16; k++)
            fma16(acc, *(float4*)&As[k][ty*4], *(float4*)&Bs[k][tx*4]);
        __syncthreads();
    }
    #pragma unroll
    for (int i = 0; i < 4; i++) {
        int p = m0 + ty*4 + i;
        if (p >= PP) continue;
        #pragma unroll
        for (int j = 0; j < 4; j++) {
            int q = n0 + tx*4 + j;
            if (q < PP) atomicAdd(&g_attp[(size_t)b*PP*PP + p*PP + q], acc[i][j]*PSCALE);
        }
    }
}

// ---------------- softmax over rows of 196 -----------------------------------
__global__ void k_psoftmax() {
    int r = blockIdx.x;
    float* row = g_attp + (size_t)r * PP;
    int t = threadIdx.x;
    float v = (t < PP) ? row[t] : -1e30f;
    __shared__ float sh[256];
    sh[t] = v; __syncthreads();
    for (int o = 128; o; o >>= 1) { if (t < o) sh[t] = fmaxf(sh[t], sh[t+o]); __syncthreads(); }
    float m = sh[0]; __syncthreads();
    float e = (t < PP) ? __expf(v - m) : 0.f;
    sh[t] = e; __syncthreads();
    for (int o = 128; o; o >>= 1) { if (t < o) sh[t] += sh[t+o]; __syncthreads(); }
    float inv = 1.f / sh[0];
    if (t < PP) row[t] = e * inv;
}

// ---------------- h_patch = V @ att^T, scaled by 0.75, into g_h --------------
__global__ void __launch_bounds__(256) k_ph() {
    __shared__ float As[16][68], Bs[16][68];
    int b = blockIdx.z;
    int m0 = blockIdx.x * 64;              // d
    int n0 = blockIdx.y * 64;              // p_out
    const float* V   = g_v + (size_t)b*CHW;       // [16384,196]
    const float* Att = g_attp + (size_t)b*PP*PP;  // [196,196]
    int tid = threadIdx.x;
    int tx = tid & 15, ty = tid >> 4;
    int lm = tid & 63, lk4 = (tid >> 6) << 2;
    const float4 z4 = make_float4(0,0,0,0);
    float acc[4][4] = {};
    for (int k0 = 0; k0 < PP; k0 += 16) {
        int kc = k0 + lk4;
        float4 a = (kc < PP) ? *(const float4*)&V[(size_t)(m0+lm)*PP + kc] : z4;
        float4 bv = (kc < PP && (n0+lm) < PP) ? *(const float4*)&Att[(size_t)(n0+lm)*PP + kc] : z4;
        As[lk4+0][lm] = a.x; As[lk4+1][lm] = a.y; As[lk4+2][lm] = a.z; As[lk4+3][lm] = a.w;
        Bs[lk4+0][lm] = bv.x; Bs[lk4+1][lm] = bv.y; Bs[lk4+2][lm] = bv.z; Bs[lk4+3][lm] = bv.w;
        __syncthreads();
        #pragma unroll
        for (int k = 0; k < 16; k++)
            fma16(acc, *(float4*)&As[k][ty*4], *(float4*)&Bs[k][tx*4]);
        __syncthreads();
    }
    #pragma unroll
    for (int i = 0; i < 4; i++) {
        int d = m0 + ty*4 + i;
        #pragma unroll
        for (int j = 0; j < 4; j++) {
            int p = n0 + tx*4 + j;
            if (p < PP) g_h[(size_t)b*CHW + (size_t)d*PP + p] = 0.75f * acc[i][j];
        }
    }
}

// ---------------- 2x2 average pool q,k,v -> qp,kp,vp -------------------------
__global__ void k_pool(int which) {
    const float* src = which == 0 ? g_q : (which == 1 ? g_k : g_v);
    float* dst       = which == 0 ? g_qp : (which == 1 ? g_kp : g_vp);
    int idx = blockIdx.x*blockDim.x + threadIdx.x;
    if (idx >= BB*CCH*AA) return;
    int x = idx % TG;
    int y = (idx / TG) % TG;
    int bc = idx / AA;
    const float* s = src + (size_t)bc*HW + (size_t)(2*y)*WWI + 2*x;
    dst[idx] = 0.25f * (s[0] + s[1] + s[WWI] + s[WWI+1]);
}

// ---------------- global scores: att[p,q] = scale*sum_c Qp[c,p]Kp[c,q] -------
__global__ void __launch_bounds__(256) k_gscore() {
    __shared__ float As[16][68], Bs[16][68];
    int b = blockIdx.z;
    int m0 = blockIdx.y * 64, n0 = blockIdx.x * 64;
    const float* Q = g_qp + (size_t)b*CA;   // [256, 3136]
    const float* K = g_kp + (size_t)b*CA;
    int tid = threadIdx.x;
    int tx = tid & 15, ty = tid >> 4;
    int lk = tid >> 4, ln = (tid & 15) << 2;
    float acc[4][4] = {};
    for (int k0 = 0; k0 < 256; k0 += 16) {
        *(float4*)&As[lk][ln] = *(const float4*)&Q[(size_t)(k0+lk)*AA + m0 + ln];
        *(float4*)&Bs[lk][ln] = *(const float4*)&K[(size_t)(k0+lk)*AA + n0 + ln];
        __syncthreads();
        #pragma unroll
        for (int k = 0; k < 16; k++)
            fma16(acc, *(float4*)&As[k][ty*4], *(float4*)&Bs[k][tx*4]);
        __syncthreads();
    }
    float* O = g_attg + (size_t)b*AA*AA;
    #pragma unroll
    for (int i = 0; i < 4; i++) {
        int p = m0 + ty*4 + i;
        float4 r = make_float4(acc[i][0]*GSCALE, acc[i][1]*GSCALE, acc[i][2]*GSCALE, acc[i][3]*GSCALE);
        *(float4*)&O[(size_t)p*AA + n0 + tx*4] = r;
    }
}

// ---------------- global softmax over rows of 3136 ---------------------------
__global__ void k_gsoftmax() {
    float* row = g_attg + (size_t)blockIdx.x * AA;
    int t = threadIdx.x;
    float v[13];
    float mx = -1e30f;
    #pragma unroll
    for (int i = 0; i < 13; i++) {
        int c = t + i*256;
        v[i] = (c < AA) ? row[c] : -1e30f;
        mx = fmaxf(mx, v[i]);
    }
    __shared__ float sh[256];
    sh[t] = mx; __syncthreads();
    for (int o = 128; o; o >>= 1) { if (t < o) sh[t] = fmaxf(sh[t], sh[t+o]); __syncthreads(); }
    float m = sh[0]; __syncthreads();
    float s = 0.f;
    #pragma unroll
    for (int i = 0; i < 13; i++) {
        int c = t + i*256;
        if (c < AA) { v[i] = __expf(v[i] - m); s += v[i]; }
    }
    sh[t] = s; __syncthreads();
    for (int o = 128; o; o >>= 1) { if (t < o) sh[t] += sh[t+o]; __syncthreads(); }
    float inv = 1.f / sh[0];
    #pragma unroll
    for (int i = 0; i < 13; i++) {
        int c = t + i*256;
        if (c < AA) row[c] = v[i] * inv;
    }
}

// ---------------- h_glob = Vp @ att^T  -> g_hg [256,3136] --------------------
__global__ void __launch_bounds__(256) k_gh() {
    __shared__ float As[16][68], Bs[16][68];
    int b = blockIdx.z;
    int n0 = blockIdx.x * 64;              // p_out  (49 tiles)
    int m0 = blockIdx.y * 64;              // c      (4 tiles)
    const float* V   = g_vp + (size_t)b*CA;        // [256,3136], contiguous k
    const float* Att = g_attg + (size_t)b*AA*AA;   // [3136,3136], contiguous k
    int tid = threadIdx.x;
    int tx = tid & 15, ty = tid >> 4;
    int lm = tid & 63, lk4 = (tid >> 6) << 2;
    float acc[4][4] = {};
    for (int k0 = 0; k0 < AA; k0 += 16) {
        float4 a  = *(const float4*)&V[(size_t)(m0+lm)*AA + k0 + lk4];
        float4 bv = *(const float4*)&Att[(size_t)(n0+lm)*AA + k0 + lk4];
        As[lk4+0][lm] = a.x; As[lk4+1][lm] = a.y; As[lk4+2][lm] = a.z; As[lk4+3][lm] = a.w;
        Bs[lk4+0][lm] = bv.x; Bs[lk4+1][lm] = bv.y; Bs[lk4+2][lm] = bv.z; Bs[lk4+3][lm] = bv.w;
        __syncthreads();
        #pragma unroll
        for (int k = 0; k < 16; k++)
            fma16(acc, *(float4*)&As[k][ty*4], *(float4*)&Bs[k][tx*4]);
        __syncthreads();
    }
    float* O = g_hg + (size_t)b*CA;
    #pragma unroll
    for (int i = 0; i < 4; i++) {
        int c = m0 + ty*4 + i;
        *(float4*)&O[(size_t)c*AA + n0 + tx*4] = *(float4*)&acc[i][0];
    }
}

// ---------------- g_h += 0.25 * bilinear_up2x(g_hg) --------------------------
__global__ void k_comb() {
    int idx = blockIdx.x*blockDim.x + threadIdx.x;
    if (idx >= BB*CHW) return;
    int xj = idx % WWI;
    int yi = (idx / WWI) % HH;
    int bc = idx / HW;
    const float* hg = g_hg + (size_t)bc*AA;
    float sy = yi*0.5f - 0.25f;
    int y0 = (int)floorf(sy);
    float fy = sy - (float)y0;
    int y0c = max(y0, 0), y1c = min(y0+1, TG-1);
    float sx = xj*0.5f - 0.25f;
    int x0 = (int)floorf(sx);
    float fx = sx - (float)x0;
    int x0c = max(x0, 0), x1c = min(x0+1, TG-1);
    float v = (1.f-fy) * ((1.f-fx)*hg[y0c*TG + x0c] + fx*hg[y0c*TG + x1c])
            +      fy  * ((1.f-fx)*hg[y1c*TG + x0c] + fx*hg[y1c*TG + x1c]);
    g_h[idx] += 0.25f * v;
}

// ---------------- out = x + Wproj @ h ----------------------------------------
__global__ void __launch_bounds__(256) k_proj(const float* __restrict__ x,
                                              const float* __restrict__ Wp,
                                              float* __restrict__ out) {
    __shared__ float As[16][68], Bs[16][68];
    int b = blockIdx.z;
    int n0 = blockIdx.x * 64;
    int m0 = blockIdx.y * 64;
    const float* Hh = g_h + (size_t)b*CHW;
    int tid = threadIdx.x;
    int tx = tid & 15, ty = tid >> 4;
    int lm = tid & 63, lk4 = (tid >> 6) << 2;
    int lbk = tid >> 4, lbn = (tid & 15) << 2;
    float acc[4][4] = {};
    for (int k0 = 0; k0 < 256; k0 += 16) {
        float4 a = *(const float4*)&Wp[(m0+lm)*256 + k0 + lk4];
        As[lk4+0][lm] = a.x; As[lk4+1][lm] = a.y; As[lk4+2][lm] = a.z; As[lk4+3][lm] = a.w;
        *(float4*)&Bs[lbk][lbn] = *(const float4*)&Hh[(size_t)(k0+lbk)*HW + n0 + lbn];
        __syncthreads();
        #pragma unroll
        for (int k = 0; k < 16; k++)
            fma16(acc, *(float4*)&As[k][ty*4], *(float4*)&Bs[k][tx*4]);
        __syncthreads();
    }
    #pragma unroll
    for (int i = 0; i < 4; i++) {
        int o = m0 + ty*4 + i;
        size_t off = (size_t)b*CHW + (size_t)o*HW + n0 + tx*4;
        float4 xr = *(const float4*)&x[off];
        float4 r = make_float4(acc[i][0]+xr.x, acc[i][1]+xr.y, acc[i][2]+xr.z, acc[i][3]+xr.w);
        *(float4*)&out[off] = r;
    }
}

// ---------------- launch ------------------------------------------------------
extern "C" void kernel_launch(void* const* d_in, const int* in_sizes, int n_in,
                              void* d_out, int out_size) {
    const float* x  = (const float*)d_in[0];
    const float* gw = (const float*)d_in[1];
    const float* gb = (const float*)d_in[2];
    const float* wq = (const float*)d_in[3];
    const float* bq = (const float*)d_in[4];
    const float* wk = (const float*)d_in[5];
    const float* bk = (const float*)d_in[6];
    const float* wv = (const float*)d_in[7];
    const float* bv = (const float*)d_in[8];
    const float* wp = (const float*)d_in[9];
    float* out = (float*)d_out;

    k_zero_small<<<64, 256>>>();
    k_gnstats<<<dim3(64, 8), 256>>>(x);
    k_gnfin<<<1, 32>>>();
    k_norm<<<BB*CCH, 256>>>(x, gw, gb);
    k_qkv<<<dim3(196, 12, 8), 256>>>(wq, bq, wk, bk, wv, bv);

    // patch branch
    k_pscore<<<dim3(4, 4, 8*16), 256>>>();
    k_psoftmax<<<BB*PP, 256>>>();
    k_ph<<<dim3(256, 4, 8), 256>>>();

    // global branch
    k_pool<<<(BB*CCH*AA + 255)/256, 256>>>(0);
    k_pool<<<(BB*CCH*AA + 255)/256, 256>>>(1);
    k_pool<<<(BB*CCH*AA + 255)/256, 256>>>(2);
    k_gscore<<<dim3(49, 49, 8), 256>>>();
    k_gsoftmax<<<BB*AA, 256>>>();
    k_gh<<<dim3(49, 4, 8), 256>>>();

    // combine + project + residual
    k_comb<<<(BB*CHW + 255)/256, 256>>>();
    k_proj<<<dim3(196, 4, 8), 256>>>(x, wp, out);
}

// round 9
// speedup vs baseline: 2.4516x; 2.4516x over previous
#include <cuda_runtime.h>
#include <cuda_bf16.h>
#include <stdint.h>
#include <math.h>
#define BB 8
#define CCH 256
#define HW 12544
#define CHW 3211264
#define PP 196
#define TG 56
#define AA 3136
#define PSCALE 0.0078125f
#define GSCALE 0.0625f
#define BKP 40
typedef __nv_bfloat16 bf16;

__device__ bf16  g_xnT[(size_t)BB*HW*CCH];
__device__ bf16  g_qT [(size_t)BB*HW*CCH];
__device__ bf16  g_kT [(size_t)BB*HW*CCH];
__device__ bf16  g_v  [(size_t)BB*HW*CCH];
__device__ bf16  g_hp [(size_t)BB*HW*CCH];
__device__ bf16  g_hT [(size_t)BB*HW*CCH];
__device__ bf16  g_qpT[(size_t)BB*AA*CCH];
__device__ bf16  g_kpT[(size_t)BB*AA*CCH];
__device__ bf16  g_vp [(size_t)BB*CCH*AA];
__device__ float g_hg [(size_t)BB*CCH*AA];
__device__ float g_attp4[(size_t)4*BB*PP*PP];
__device__ bf16  g_attpb[(size_t)BB*PP*PP];
__device__ float g_attg[(size_t)BB*AA*AA];
__device__ bf16  g_attgb[(size_t)BB*AA*AA];
__device__ double g_sum[BB], g_sq[BB];
__device__ float g_mean[BB], g_rstd[BB];

__device__ __forceinline__ uint32_t s2u(const void* p){
  uint32_t a; asm("{ .reg .u64 t; cvta.to.shared.u64 t, %1; cvt.u32.u64 %0, t; }":"=r"(a):"l"(p)); return a; }
__device__ __forceinline__ uint32_t pk(float x,float y){ __nv_bfloat162 h=__floats2bfloat162_rn(x,y); return *(uint32_t*)&h; }
__device__ __forceinline__ unsigned short bfr(float f){ bf16 h=__float2bfloat16(f); return *(unsigned short*)&h; }

// stage 128 rows x 32 bf16-k into smem pitch BKP
__device__ __forceinline__ void ld16(bf16* d,const bf16* s,int pitch,int r0,int rmax,int tid){
  #pragma unroll
  for(int i=0;i<2;i++){
    int sl=tid+i*256,r=sl>>2,ch=sl&3,gr=r0+r; gr=gr>rmax?rmax:gr;
    uint4 v=*(const uint4*)(s+(size_t)gr*pitch+ch*8);
    *(uint4*)(d+r*BKP+ch*8)=v;
  } }
__device__ __forceinline__ void ld8(bf16* d,const bf16* s,int pitch,int r0,int rmax,int k0,int kmax,int tid){
  #pragma unroll
  for(int i=0;i<2;i++){
    int sl=tid+i*256,r=sl>>2,ch=sl&3,gr=r0+r; gr=gr>rmax?rmax:gr;
    int gk=k0+ch*8; const bf16* p=s+(size_t)gr*pitch+gk; uint4 v;
    if(gk+8<=kmax){ uint2 lo=*(const uint2*)p,hi=*(const uint2*)(p+4); v=make_uint4(lo.x,lo.y,hi.x,hi.y); }
    else{ unsigned short t8[8];
      #pragma unroll
      for(int e=0;e<8;e++) t8[e]=(gk+e<kmax)?*(const unsigned short*)(p+e):(unsigned short)0;
      v=*(uint4*)t8; }
    *(uint4*)(d+r*BKP+ch*8)=v;
  } }
__device__ __forceinline__ void ldw(bf16* d,const float* s,int pitch,int r0,int k0,int tid){
  #pragma unroll
  for(int i=0;i<2;i++){
    int sl=tid+i*256,r=sl>>2,ch=sl&3;
    const float* p=s+(size_t)(r0+r)*pitch+k0+ch*8;
    float4 a4=*(const float4*)p,b4=*(const float4*)(p+4);
    uint4 v; v.x=pk(a4.x,a4.y); v.y=pk(a4.z,a4.w); v.z=pk(b4.x,b4.y); v.w=pk(b4.z,b4.w);
    *(uint4*)(d+r*BKP+ch*8)=v;
  } }

__device__ __forceinline__ void mma_tile(float (&c)[4][4][4],uint32_t smbA,uint32_t smbB,int w,int lane){
  int wm=(w&1)*64, wn=(w>>1)*32;
  #pragma unroll
  for(int ks=0;ks<2;ks++){
    uint32_t a[4][4],bv[4][2];
    #pragma unroll
    for(int mi=0;mi<4;mi++){
      uint32_t ad=smbA+((wm+mi*16+(lane&15))*BKP+ks*16+(lane>>4)*8)*2;
      asm volatile("ldmatrix.sync.aligned.m8n8.x4.shared.b16 {%0,%1,%2,%3},[%4];"
        :"=r"(a[mi][0]),"=r"(a[mi][1]),"=r"(a[mi][2]),"=r"(a[mi][3]):"r"(ad));
    }
    #pragma unroll
    for(int ni=0;ni<4;ni++){
      uint32_t bd=smbB+((wn+ni*8+(lane&7))*BKP+ks*16+((lane>>3)&1)*8)*2;
      asm volatile("ldmatrix.sync.aligned.m8n8.x2.shared.b16 {%0,%1},[%2];"
        :"=r"(bv[ni][0]),"=r"(bv[ni][1]):"r"(bd));
    }
    #pragma unroll
    for(int mi=0;mi<4;mi++)
      #pragma unroll
      for(int ni=0;ni<4;ni++)
        asm volatile("mma.sync.aligned.m16n8k16.row.col.f32.bf16.bf16.f32 {%0,%1,%2,%3},{%4,%5,%6,%7},{%8,%9},{%0,%1,%2,%3};"
          :"+f"(c[mi][ni][0]),"+f"(c[mi][ni][1]),"+f"(c[mi][ni][2]),"+f"(c[mi][ni][3])
          :"r"(a[mi][0]),"r"(a[mi][1]),"r"(a[mi][2]),"r"(a[mi][3]),"r"(bv[ni][0]),"r"(bv[ni][1]));
  } }

__device__ __forceinline__ void dump_chunk(float* Cs,int w,int lane,int j,float (&c)[4][4][4]){
  if((w>>1)==j){
    int wm=(w&1)*64;
    #pragma unroll
    for(int mi=0;mi<4;mi++)
      #pragma unroll
      for(int ni=0;ni<4;ni++){
        int r=wm+mi*16+(lane>>2), cc=ni*8+(lane&3)*2;
        Cs[r*33+cc]=c[mi][ni][0]; Cs[r*33+cc+1]=c[mi][ni][1];
        Cs[(r+8)*33+cc]=c[mi][ni][2]; Cs[(r+8)*33+cc+1]=c[mi][ni][3];
      }
  } }

#define GEMM_PRE \
  __shared__ __align__(16) char smch[20480]; \
  bf16* As=(bf16*)smch; bf16* Bs=(bf16*)(smch+10240); float* Cs=(float*)smch; \
  uint32_t smbA=s2u(As),smbB=s2u(Bs); \
  int t=threadIdx.x,w=t>>5,lane=t&31,m_=t&127,grp=t>>7; \
  float c[4][4][4]={};

__global__ void k_zero(){ int t=threadIdx.x; if(t<BB){ g_sum[t]=0.0; g_sq[t]=0.0; } }
__global__ void k_gnstats(const float* __restrict__ x){
  int b=blockIdx.y; const float4* xb=(const float4*)(x+(size_t)b*CHW);
  float s=0.f,ss=0.f;
  for(int i=blockIdx.x*blockDim.x+threadIdx.x;i<CHW/4;i+=gridDim.x*blockDim.x){
    float4 v=xb[i]; s+=v.x+v.y+v.z+v.w; ss+=v.x*v.x+v.y*v.y+v.z*v.z+v.w*v.w; }
  __shared__ double sh[256],sh2[256];
  sh[threadIdx.x]=(double)s; sh2[threadIdx.x]=(double)ss; __syncthreads();
  for(int o=128;o>0;o>>=1){ if(threadIdx.x<o){ sh[threadIdx.x]+=sh[threadIdx.x+o]; sh2[threadIdx.x]+=sh2[threadIdx.x+o]; } __syncthreads(); }
  if(threadIdx.x==0){ atomicAdd(&g_sum[b],sh[0]); atomicAdd(&g_sq[b],sh2[0]); } }
__global__ void k_gnfin(){
  int b=threadIdx.x;
  if(b<BB){ double n=(double)CHW,mu=g_sum[b]/n,var=g_sq[b]/n-mu*mu;
    g_mean[b]=(float)mu; g_rstd[b]=(float)rsqrt(var+1e-5); } }

__global__ void __launch_bounds__(256) k_normT(const float* __restrict__ x,const float* __restrict__ gw,const float* __restrict__ gb){
  __shared__ bf16 sm[32][132];
  int b=blockIdx.z,c0=blockIdx.y*32,hw0=blockIdx.x*128,t=threadIdx.x;
  float mu=g_mean[b],rs=g_rstd[b];
  #pragma unroll
  for(int i=0;i<4;i++){
    int r=i*8+(t>>5),ch=t&31,c=c0+r;
    float sc=rs*gw[c],sh=gb[c]-mu*sc;
    float4 v=*(const float4*)(x+(size_t)b*CHW+(size_t)c*HW+hw0+ch*4);
    sm[r][ch*4+0]=__float2bfloat16(v.x*sc+sh); sm[r][ch*4+1]=__float2bfloat16(v.y*sc+sh);
    sm[r][ch*4+2]=__float2bfloat16(v.z*sc+sh); sm[r][ch*4+3]=__float2bfloat16(v.w*sc+sh);
  }
  __syncthreads();
  bf16* dst=g_xnT+(size_t)b*HW*CCH;
  #pragma unroll
  for(int i=0;i<2;i++){
    int sl=t+i*256,j=sl>>2,part=sl&3; unsigned short tmp[8];
    #pragma unroll
    for(int e=0;e<8;e++) tmp[e]=*(unsigned short*)&sm[part*8+e][j];
    *(uint4*)(dst+(size_t)(hw0+j)*CCH+c0+part*8)=*(uint4*)tmp;
  } }

__global__ void __launch_bounds__(256) k_qkv_mm(const float* __restrict__ wq,const float* __restrict__ bq,
    const float* __restrict__ wk,const float* __restrict__ bk,const float* __restrict__ wv,const float* __restrict__ bv){
  GEMM_PRE
  int b=blockIdx.z,mb=blockIdx.y,n0=blockIdx.x*128,seg=mb>>1,o0=(mb&1)*128;
  const float* W=seg==0?wq:(seg==1?wk:wv);
  const float* Bi=seg==0?bq:(seg==1?bk:bv);
  const bf16* X=g_xnT+(size_t)b*HW*CCH;
  for(int kt=0;kt<8;kt++){
    ldw(As,W,CCH,o0,kt*32,t);
    ld16(Bs,X+kt*32,CCH,n0,HW-1,t);
    __syncthreads(); mma_tile(c,smbA,smbB,w,lane); __syncthreads();
  }
  int o=o0+m_; float bias=Bi[o];
  for(int j=0;j<4;j++){
    __syncthreads(); dump_chunk(Cs,w,lane,j,c); __syncthreads();
    if(seg<2){
      bf16* dst=(seg?g_kT:g_qT)+(size_t)b*HW*CCH;
      #pragma unroll
      for(int e=0;e<16;e++){
        int n=n0+j*32+grp*16+e;
        dst[(size_t)n*CCH+o]=__float2bfloat16(Cs[m_*33+grp*16+e]+bias);
      }
    }else{
      bf16* dst=g_v+(size_t)b*HW*CCH+(size_t)o*HW;
      unsigned short buf[16];
      #pragma unroll
      for(int e=0;e<16;e++) buf[e]=bfr(Cs[m_*33+grp*16+e]+bias);
      *(uint4*)(dst+n0+j*32+grp*16)=*(uint4*)buf;
      *(uint4*)(dst+n0+j*32+grp*16+8)=*(uint4*)(buf+8);
    }
  } }

__global__ void __launch_bounds__(256) k_pscore_mm(){
  GEMM_PRE
  int z=blockIdx.z,b=z>>2,ks=z&3,m0=blockIdx.y*128,n0=blockIdx.x*128;
  const bf16* Q=g_qT+(size_t)b*HW*CCH;
  const bf16* K=g_kT+(size_t)b*HW*CCH;
  for(int it=0;it<128;it++){
    int s=ks*16+(it>>3),kc=it&7;
    ld16(As,Q+(size_t)s*PP*CCH+kc*32,CCH,m0,PP-1,t);
    ld16(Bs,K+(size_t)s*PP*CCH+kc*32,CCH,n0,PP-1,t);
    __syncthreads(); mma_tile(c,smbA,smbB,w,lane); __syncthreads();
  }
  int p=m0+m_;
  float* dst=g_attp4+((size_t)(ks*BB+b)*PP+(p<PP?p:0))*PP;
  for(int j=0;j<4;j++){
    __syncthreads(); dump_chunk(Cs,w,lane,j,c); __syncthreads();
    if(p<PP){
      #pragma unroll
      for(int e=0;e<16;e++){
        int q=n0+j*32+grp*16+e;
        if(q<PP) dst[q]=Cs[m_*33+grp*16+e]*PSCALE;
      }
    }
  } }

__global__ void k_psoftmax(){
  int p=blockIdx.x,b=blockIdx.y,t=threadIdx.x;
  float v=-1e30f;
  if(t<PP){ v=0.f;
    #pragma unroll
    for(int ks=0;ks<4;ks++) v+=g_attp4[((size_t)(ks*BB+b)*PP+p)*PP+t]; }
  __shared__ float sh[256];
  sh[t]=v; __syncthreads();
  for(int o=128;o;o>>=1){ if(t<o) sh[t]=fmaxf(sh[t],sh[t+o]); __syncthreads(); }
  float m=sh[0]; __syncthreads();
  float e=(t<PP)?__expf(v-m):0.f;
  sh[t]=e; __syncthreads();
  for(int o=128;o;o>>=1){ if(t<o) sh[t]+=sh[t+o]; __syncthreads(); }
  float inv=1.f/sh[0];
  if(t<PP) g_attpb[((size_t)b*PP+p)*PP+t]=__float2bfloat16(e*inv); }

__global__ void __launch_bounds__(256) k_ph_mm(){
  GEMM_PRE
  int b=blockIdx.z,m0=blockIdx.y*128,n0=blockIdx.x*128;
  const bf16* V=g_v+(size_t)b*HW*CCH;
  const bf16* A=g_attpb+(size_t)b*PP*PP;
  for(int kt=0;kt<7;kt++){
    ld8(As,V,PP,m0,16383,kt*32,PP,t);
    ld8(Bs,A,PP,n0,PP-1,kt*32,PP,t);
    __syncthreads(); mma_tile(c,smbA,smbB,w,lane); __syncthreads();
  }
  int d=m0+m_;
  bf16* dst=g_hp+(size_t)b*HW*CCH+(size_t)d*PP;
  for(int j=0;j<4;j++){
    __syncthreads(); dump_chunk(Cs,w,lane,j,c); __syncthreads();
    #pragma unroll
    for(int e=0;e<16;e++){
      int p=n0+j*32+grp*16+e;
      if(p<PP) dst[p]=__float2bfloat16(Cs[m_*33+grp*16+e]);
    }
  } }

__global__ void k_pool_qk(){
  int a=blockIdx.x,b=blockIdx.y,c=threadIdx.x,y=a/TG,x=a%TG;
  size_t h00=(size_t)(2*y*112+2*x)*CCH+c;
  const bf16* Q=g_qT+(size_t)b*HW*CCH;
  const bf16* K=g_kT+(size_t)b*HW*CCH;
  float qv=0.25f*(__bfloat162float(Q[h00])+__bfloat162float(Q[h00+CCH])+__bfloat162float(Q[h00+112*CCH])+__bfloat162float(Q[h00+113*CCH]));
  float kv=0.25f*(__bfloat162float(K[h00])+__bfloat162float(K[h00+CCH])+__bfloat162float(K[h00+112*CCH])+__bfloat162float(K[h00+113*CCH]));
  g_qpT[((size_t)b*AA+a)*CCH+c]=__float2bfloat16(qv);
  g_kpT[((size_t)b*AA+a)*CCH+c]=__float2bfloat16(kv); }
__global__ void k_pool_v(){
  int c=blockIdx.x,b=blockIdx.y,t=threadIdx.x;
  const bf16* V=g_v+(size_t)b*HW*CCH+(size_t)c*HW;
  bf16* dst=g_vp+((size_t)b*CCH+c)*AA;
  for(int i=0;i<13;i++){
    int a=t+i*256;
    if(a<AA){
      int y=a/TG,x=a%TG,h00=2*y*112+2*x;
      float v=0.25f*(__bfloat162float(V[h00])+__bfloat162float(V[h00+1])+__bfloat162float(V[h00+112])+__bfloat162float(V[h00+113]));
      dst[a]=__float2bfloat16(v);
    }
  } }

__global__ void __launch_bounds__(256) k_gscore_mm(){
  GEMM_PRE
  int b=blockIdx.z,m0=blockIdx.y*128,n0=blockIdx.x*128;
  const bf16* Q=g_qpT+(size_t)b*AA*CCH;
  const bf16* K=g_kpT+(size_t)b*AA*CCH;
  for(int kt=0;kt<8;kt++){
    ld16(As,Q+kt*32,CCH,m0,AA-1,t);
    ld16(Bs,K+kt*32,CCH,n0,AA-1,t);
    __syncthreads(); mma_tile(c,smbA,smbB,w,lane); __syncthreads();
  }
  int p=m0+m_;
  float* dst=g_attg+((size_t)b*AA+(p<AA?p:0))*AA;
  for(int j=0;j<4;j++){
    __syncthreads(); dump_chunk(Cs,w,lane,j,c); __syncthreads();
    if(p<AA){
      #pragma unroll
      for(int e=0;e<16;e++){
        int q=n0+j*32+grp*16+e;
        if(q<AA) dst[q]=Cs[m_*33+grp*16+e]*GSCALE;
      }
    }
  } }

__global__ void k_gsoftmax(){
  size_t row=(size_t)blockIdx.y*AA+blockIdx.x;
  const float* src=g_attg+row*AA;
  bf16* dst=g_attgb+row*AA;
  int t=threadIdx.x;
  float v[13],mx=-1e30f;
  #pragma unroll
  for(int i=0;i<13;i++){ int c=t+i*256; v[i]=(c<AA)?src[c]:-1e30f; mx=fmaxf(mx,v[i]); }
  __shared__ float sh[256];
  sh[t]=mx; __syncthreads();
  for(int o=128;o;o>>=1){ if(t<o) sh[t]=fmaxf(sh[t],sh[t+o]); __syncthreads(); }
  float m=sh[0]; __syncthreads();
  float s=0.f;
  #pragma unroll
  for(int i=0;i<13;i++){ int c=t+i*256; if(c<AA){ v[i]=__expf(v[i]-m); s+=v[i]; } }
  sh[t]=s; __syncthreads();
  for(int o=128;o;o>>=1){ if(t<o) sh[t]+=sh[t+o]; __syncthreads(); }
  float inv=1.f/sh[0];
  #pragma unroll
  for(int i=0;i<13;i++){ int c=t+i*256; if(c<AA) dst[c]=__float2bfloat16(v[i]*inv); } }

__global__ void __launch_bounds__(256) k_gh_mm(){
  GEMM_PRE
  int b=blockIdx.z,m0=blockIdx.y*128,n0=blockIdx.x*128;
  const bf16* V=g_vp+(size_t)b*CCH*AA;
  const bf16* A=g_attgb+(size_t)b*AA*AA;
  for(int kt=0;kt<98;kt++){
    ld16(As,V+kt*32,AA,m0,CCH-1,t);
    ld16(Bs,A+kt*32,AA,n0,AA-1,t);
    __syncthreads(); mma_tile(c,smbA,smbB,w,lane); __syncthreads();
  }
  int cc=m0+m_;
  float* dst=g_hg+((size_t)b*CCH+cc)*AA;
  for(int j=0;j<4;j++){
    __syncthreads(); dump_chunk(Cs,w,lane,j,c); __syncthreads();
    #pragma unroll
    for(int e=0;e<16;e++){
      int a=n0+j*32+grp*16+e;
      if(a<AA) dst[a]=Cs[m_*33+grp*16+e];
    }
  } }

__global__ void __launch_bounds__(256) k_comb(){
  __shared__ bf16 sm[32][132];
  int b=blockIdx.z,c0=blockIdx.y*32,hw0=blockIdx.x*128,t=threadIdx.x;
  #pragma unroll
  for(int i=0;i<4;i++){
    int r=i*8+(t>>5),ch=t&31,c=c0+r;
    const bf16* hp=g_hp+(size_t)b*HW*CCH+(size_t)c*HW+hw0+ch*4;
    const float* hg=g_hg+((size_t)b*CCH+c)*AA;
    uint2 raw=*(const uint2*)hp; bf16 hpv[4]; *(uint2*)hpv=raw;
    #pragma unroll
    for(int e=0;e<4;e++){
      int hw=hw0+ch*4+e,yi=hw/112,xj=hw%112;
      float sy=yi*0.5f-0.25f; int y0=(int)floorf(sy); float fy=sy-(float)y0;
      int y0c=max(y0,0),y1c=min(y0+1,TG-1);
      float sx=xj*0.5f-0.25f; int x0=(int)floorf(sx); float fx=sx-(float)x0;
      int x0c=max(x0,0),x1c=min(x0+1,TG-1);
      float hv=(1.f-fy)*((1.f-fx)*hg[y0c*TG+x0c]+fx*hg[y0c*TG+x1c])+fy*((1.f-fx)*hg[y1c*TG+x0c]+fx*hg[y1c*TG+x1c]);
      sm[r][ch*4+e]=__float2bfloat16(0.75f*__bfloat162float(hpv[e])+0.25f*hv);
    }
  }
  __syncthreads();
  bf16* dst=g_hT+(size_t)b*HW*CCH;
  #pragma unroll
  for(int i=0;i<2;i++){
    int sl=t+i*256,j=sl>>2,part=sl&3; unsigned short tmp[8];
    #pragma unroll
    for(int e=0;e<8;e++) tmp[e]=*(unsigned short*)&sm[part*8+e][j];
    *(uint4*)(dst+(size_t)(hw0+j)*CCH+c0+part*8)=*(uint4*)tmp;
  } }

__global__ void __launch_bounds__(256) k_proj_mm(const float* __restrict__ x,const float* __restrict__ wp,float* __restrict__ out){
  GEMM_PRE
  int b=blockIdx.z,o0=blockIdx.y*128,n0=blockIdx.x*128;
  const bf16* Hh=g_hT+(size_t)b*HW*CCH;
  for(int kt=0;kt<8;kt++){
    ldw(As,wp,CCH,o0,kt*32,t);
    ld16(Bs,Hh+kt*32,CCH,n0,HW-1,t);
    __syncthreads(); mma_tile(c,smbA,smbB,w,lane); __syncthreads();
  }
  int o=o0+m_;
  size_t base=(size_t)b*CHW+(size_t)o*HW;
  for(int j=0;j<4;j++){
    __syncthreads(); dump_chunk(Cs,w,lane,j,c); __syncthreads();
    #pragma unroll
    for(int e=0;e<16;e++){
      size_t off=base+n0+j*32+grp*16+e;
      out[off]=Cs[m_*33+grp*16+e]+x[off];
    }
  } }

extern "C" void kernel_launch(void* const* d_in,const int* in_sizes,int n_in,void* d_out,int out_size){
  const float* x =(const float*)d_in[0];
  const float* gw=(const float*)d_in[1];
  const float* gb=(const float*)d_in[2];
  const float* wq=(const float*)d_in[3];
  const float* bq=(const float*)d_in[4];
  const float* wk=(const float*)d_in[5];
  const float* bk=(const float*)d_in[6];
  const float* wv=(const float*)d_in[7];
  const float* bv=(const float*)d_in[8];
  const float* wp=(const float*)d_in[9];
  float* out=(float*)d_out;
  k_zero<<<1,32>>>();
  k_gnstats<<<dim3(64,8),256>>>(x);
  k_gnfin<<<1,32>>>();
  k_normT<<<dim3(98,8,8),256>>>(x,gw,gb);
  k_qkv_mm<<<dim3(98,6,8),256>>>(wq,bq,wk,bk,wv,bv);
  k_pscore_mm<<<dim3(2,2,32),256>>>();
  k_psoftmax<<<dim3(PP,BB),256>>>();
  k_ph_mm<<<dim3(2,128,8),256>>>();
  k_pool_qk<<<dim3(AA,BB),256>>>();
  k_pool_v<<<dim3(CCH,BB),256>>>();
  k_gscore_mm<<<dim3(25,25,8),256>>>();
  k_gsoftmax<<<dim3(AA,BB),256>>>();
  k_gh_mm<<<dim3(25,2,8),256>>>();
  k_comb<<<dim3(98,8,8),256>>>();
  k_proj_mm<<<dim3(98,2,8),256>>>(x,wp,out);
}

// round 12
// speedup vs baseline: 2.7141x; 1.1071x over previous
#include <cuda_runtime.h>
#include <cuda_bf16.h>
#include <stdint.h>
#include <math.h>
#define BB 8
#define CCH 256
#define HW 12544
#define CHW 3211264
#define PP 196
#define TG 56
#define AA 3136
#define PSCALE 0.0078125f
#define GSCALE 0.0625f
#define BKP 40
typedef __nv_bfloat16 bf16;

__device__ bf16  g_xnT[(size_t)BB*HW*CCH];
__device__ bf16  g_qT [(size_t)BB*HW*CCH];
__device__ bf16  g_kT [(size_t)BB*HW*CCH];
__device__ bf16  g_v  [(size_t)BB*HW*CCH];
__device__ bf16  g_hp [(size_t)BB*HW*CCH];
__device__ bf16  g_hT [(size_t)BB*HW*CCH];
__device__ bf16  g_qpT[(size_t)BB*AA*CCH];
__device__ bf16  g_kpT[(size_t)BB*AA*CCH];
__device__ bf16  g_vp [(size_t)BB*CCH*AA];
__device__ float g_hg [(size_t)BB*CCH*AA];
__device__ float g_attp4[(size_t)4*BB*PP*PP];
__device__ bf16  g_attpb[(size_t)BB*PP*PP];
__device__ float g_attg[(size_t)BB*AA*AA];
__device__ bf16  g_attgb[(size_t)BB*AA*AA];
__device__ bf16  g_wb[(size_t)4*CCH*CCH];
__device__ double g_sum[BB], g_sq[BB];
__device__ float g_mean[BB], g_rstd[BB];

__device__ __forceinline__ uint32_t s2u(const void* p){
  uint32_t a; asm("{ .reg .u64 t; cvta.to.shared.u64 t, %1; cvt.u32.u64 %0, t; }":"=r"(a):"l"(p)); return a; }
__device__ __forceinline__ unsigned short bfr(float f){ bf16 h=__float2bfloat16(f); return *(unsigned short*)&h; }
#define CPCOMMIT() asm volatile("cp.async.commit_group;":::"memory")
#define CPWAIT1() asm volatile("cp.async.wait_group 1;":::"memory")
#define CPWAIT0() asm volatile("cp.async.wait_group 0;":::"memory")

__device__ __forceinline__ void cp16(uint32_t db,const bf16* s,int pitch,int r0,int rmax,int tid){
  #pragma unroll
  for(int i=0;i<2;i++){
    int sl=tid+i*256,r=sl>>2,ch=sl&3,gr=r0+r; gr=gr>rmax?rmax:gr;
    asm volatile("cp.async.ca.shared.global [%0],[%1],16;"
      ::"r"(db+(uint32_t)(r*BKP+ch*8)*2),"l"(s+(size_t)gr*pitch+ch*8):"memory");
  } }
__device__ __forceinline__ void cp8(uint32_t db,const bf16* s,int pitch,int r0,int rmax,int k0,int kmax,int tid){
  #pragma unroll
  for(int i=0;i<4;i++){
    int sl=tid+i*256,r=sl>>3,ch=sl&7,gr=r0+r; gr=gr>rmax?rmax:gr;
    int gk=k0+ch*4;
    int bytes=(kmax-gk)*2; bytes=bytes<0?0:(bytes>8?8:bytes);
    int gkc=gk<kmax?gk:(kmax-1);
    asm volatile("cp.async.ca.shared.global [%0],[%1],8,%2;"
      ::"r"(db+(uint32_t)(r*BKP+ch*4)*2),"l"(s+(size_t)gr*pitch+gkc),"r"(bytes):"memory");
  } }

__device__ __forceinline__ void mma_tile(float (&c)[4][4][4],uint32_t aB,uint32_t bB,int w,int lane){
  int wm=(w&1)*64, wn=(w>>1)*32;
  #pragma unroll
  for(int ks=0;ks<2;ks++){
    uint32_t a[4][4],bv[4][2];
    #pragma unroll
    for(int mi=0;mi<4;mi++){
      uint32_t ad=aB+((wm+mi*16+(lane&15))*BKP+ks*16+(lane>>4)*8)*2;
      asm volatile("ldmatrix.sync.aligned.m8n8.x4.shared.b16 {%0,%1,%2,%3},[%4];"
        :"=r"(a[mi][0]),"=r"(a[mi][1]),"=r"(a[mi][2]),"=r"(a[mi][3]):"r"(ad));
    }
    #pragma unroll
    for(int ni=0;ni<4;ni++){
      uint32_t bd=bB+((wn+ni*8+(lane&7))*BKP+ks*16+((lane>>3)&1)*8)*2;
      asm volatile("ldmatrix.sync.aligned.m8n8.x2.shared.b16 {%0,%1},[%2];"
        :"=r"(bv[ni][0]),"=r"(bv[ni][1]):"r"(bd));
    }
    #pragma unroll
    for(int mi=0;mi<4;mi++)
      #pragma unroll
      for(int ni=0;ni<4;ni++)
        asm volatile("mma.sync.aligned.m16n8k16.row.col.f32.bf16.bf16.f32 {%0,%1,%2,%3},{%4,%5,%6,%7},{%8,%9},{%0,%1,%2,%3};"
          :"+f"(c[mi][ni][0]),"+f"(c[mi][ni][1]),"+f"(c[mi][ni][2]),"+f"(c[mi][ni][3])
          :"r"(a[mi][0]),"r"(a[mi][1]),"r"(a[mi][2]),"r"(a[mi][3]),"r"(bv[ni][0]),"r"(bv[ni][1]));
  } }

__device__ __forceinline__ void dump_chunk(float* Cs,int w,int lane,int j,float (&c)[4][4][4]){
  if((w>>1)==j){
    int wm=(w&1)*64;
    #pragma unroll
    for(int mi=0;mi<4;mi++)
      #pragma unroll
      for(int ni=0;ni<4;ni++){
        int r=wm+mi*16+(lane>>2), cc=ni*8+(lane&3)*2;
        Cs[r*33+cc]=c[mi][ni][0]; Cs[r*33+cc+1]=c[mi][ni][1];
        Cs[(r+8)*33+cc]=c[mi][ni][2]; Cs[(r+8)*33+cc+1]=c[mi][ni][3];
      }
  } }

#define GEMM_PRE \
  __shared__ __align__(16) char smch[40960]; \
  float* Cs=(float*)smch; \
  uint32_t smb=s2u(smch); \
  int t=threadIdx.x,w=t>>5,lane=t&31,m_=t&127,grp=t>>7; \
  float c[4][4][4]={};
#define ABUF(i) (smb+(uint32_t)(i)*20480u)
#define BBUF(i) (smb+(uint32_t)(i)*20480u+10240u)

__global__ void k_zero(){ int t=threadIdx.x; if(t<BB){ g_sum[t]=0.0; g_sq[t]=0.0; } }
__global__ void k_wcvt(const float* __restrict__ wq,const float* __restrict__ wk,
                       const float* __restrict__ wv,const float* __restrict__ wp){
  int i=blockIdx.x*256+threadIdx.x;
  g_wb[i]=__float2bfloat16(wq[i]);
  g_wb[65536+i]=__float2bfloat16(wk[i]);
  g_wb[131072+i]=__float2bfloat16(wv[i]);
  g_wb[196608+i]=__float2bfloat16(wp[i]); }
__global__ void k_gnstats(const float* __restrict__ x){
  int b=blockIdx.y; const float4* xb=(const float4*)(x+(size_t)b*CHW);
  float s=0.f,ss=0.f;
  for(int i=blockIdx.x*blockDim.x+threadIdx.x;i<CHW/4;i+=gridDim.x*blockDim.x){
    float4 v=xb[i]; s+=v.x+v.y+v.z+v.w; ss+=v.x*v.x+v.y*v.y+v.z*v.z+v.w*v.w; }
  __shared__ double sh[256],sh2[256];
  sh[threadIdx.x]=(double)s; sh2[threadIdx.x]=(double)ss; __syncthreads();
  for(int o=128;o>0;o>>=1){ if(threadIdx.x<o){ sh[threadIdx.x]+=sh[threadIdx.x+o]; sh2[threadIdx.x]+=sh2[threadIdx.x+o]; } __syncthreads(); }
  if(threadIdx.x==0){ atomicAdd(&g_sum[b],sh[0]); atomicAdd(&g_sq[b],sh2[0]); } }
__global__ void k_gnfin(){
  int b=threadIdx.x;
  if(b<BB){ double n=(double)CHW,mu=g_sum[b]/n,var=g_sq[b]/n-mu*mu;
    g_mean[b]=(float)mu; g_rstd[b]=(float)rsqrt(var+1e-5); } }

__global__ void __launch_bounds__(256) k_normT(const float* __restrict__ x,const float* __restrict__ gw,const float* __restrict__ gb){
  __shared__ bf16 sm[32][132];
  int b=blockIdx.z,c0=blockIdx.y*32,hw0=blockIdx.x*128,t=threadIdx.x;
  float mu=g_mean[b],rs=g_rstd[b];
  #pragma unroll
  for(int i=0;i<4;i++){
    int r=i*8+(t>>5),ch=t&31,c=c0+r;
    float sc=rs*gw[c],sh=gb[c]-mu*sc;
    float4 v=*(const float4*)(x+(size_t)b*CHW+(size_t)c*HW+hw0+ch*4);
    sm[r][ch*4+0]=__float2bfloat16(v.x*sc+sh); sm[r][ch*4+1]=__float2bfloat16(v.y*sc+sh);
    sm[r][ch*4+2]=__float2bfloat16(v.z*sc+sh); sm[r][ch*4+3]=__float2bfloat16(v.w*sc+sh);
  }
  __syncthreads();
  bf16* dst=g_xnT+(size_t)b*HW*CCH;
  #pragma unroll
  for(int i=0;i<2;i++){
    int sl=t+i*256,j=sl>>2,part=sl&3; unsigned short tmp[8];
    #pragma unroll
    for(int e=0;e<8;e++) tmp[e]=*(unsigned short*)&sm[part*8+e][j];
    *(uint4*)(dst+(size_t)(hw0+j)*CCH+c0+part*8)=*(uint4*)tmp;
  } }

__global__ void __launch_bounds__(256) k_qkv_mm(const float* __restrict__ bq,
    const float* __restrict__ bk,const float* __restrict__ bv){
  GEMM_PRE
  int b=blockIdx.z,mb=blockIdx.y,n0=blockIdx.x*128,seg=mb>>1,o0=(mb&1)*128;
  const bf16* W=g_wb+(size_t)seg*65536;
  const float* Bi=seg==0?bq:(seg==1?bk:bv);
  const bf16* X=g_xnT+(size_t)b*HW*CCH;
  cp16(ABUF(0),W,CCH,o0,255,t); cp16(BBUF(0),X,CCH,n0,HW-1,t); CPCOMMIT();
  for(int kt=0;kt<8;kt++){
    if(kt<7){ cp16(ABUF((kt+1)&1),W+(kt+1)*32,CCH,o0,255,t);
              cp16(BBUF((kt+1)&1),X+(kt+1)*32,CCH,n0,HW-1,t); CPCOMMIT(); CPWAIT1(); }
    else CPWAIT0();
    __syncthreads();
    mma_tile(c,ABUF(kt&1),BBUF(kt&1),w,lane);
    __syncthreads();
  }
  int o=o0+m_; float bias=Bi[o];
  for(int j=0;j<4;j++){
    __syncthreads(); dump_chunk(Cs,w,lane,j,c); __syncthreads();
    if(seg<2){
      bf16* dst=(seg?g_kT:g_qT)+(size_t)b*HW*CCH;
      #pragma unroll
      for(int e=0;e<16;e++){
        int n=n0+j*32+grp*16+e;
        dst[(size_t)n*CCH+o]=__float2bfloat16(Cs[m_*33+grp*16+e]+bias);
      }
    }else{
      bf16* dst=g_v+(size_t)b*HW*CCH+(size_t)o*HW;
      unsigned short buf[16];
      #pragma unroll
      for(int e=0;e<16;e++) buf[e]=bfr(Cs[m_*33+grp*16+e]+bias);
      *(uint4*)(dst+n0+j*32+grp*16)=*(uint4*)buf;
      *(uint4*)(dst+n0+j*32+grp*16+8)=*(uint4*)(buf+8);
    }
  } }

__global__ void __launch_bounds__(256) k_pscore_mm(){
  GEMM_PRE
  int z=blockIdx.z,b=z>>2,ks=z&3,m0=blockIdx.y*128,n0=blockIdx.x*128;
  const bf16* Q=g_qT+(size_t)b*HW*CCH;
  const bf16* K=g_kT+(size_t)b*HW*CCH;
  {
    int s=ks*16,kc=0;
    cp16(ABUF(0),Q+(size_t)s*PP*CCH+kc*32,CCH,m0,PP-1,t);
    cp16(BBUF(0),K+(size_t)s*PP*CCH+kc*32,CCH,n0,PP-1,t); CPCOMMIT();
  }
  for(int it=0;it<128;it++){
    if(it<127){
      int s=ks*16+((it+1)>>3),kc=(it+1)&7;
      cp16(ABUF((it+1)&1),Q+(size_t)s*PP*CCH+kc*32,CCH,m0,PP-1,t);
      cp16(BBUF((it+1)&1),K+(size_t)s*PP*CCH+kc*32,CCH,n0,PP-1,t); CPCOMMIT(); CPWAIT1();
    } else CPWAIT0();
    __syncthreads();
    mma_tile(c,ABUF(it&1),BBUF(it&1),w,lane);
    __syncthreads();
  }
  int p=m0+m_;
  float* dst=g_attp4+((size_t)(ks*BB+b)*PP+(p<PP?p:0))*PP;
  for(int j=0;j<4;j++){
    __syncthreads(); dump_chunk(Cs,w,lane,j,c); __syncthreads();
    if(p<PP){
      #pragma unroll
      for(int e=0;e<16;e++){
        int q=n0+j*32+grp*16+e;
        if(q<PP) dst[q]=Cs[m_*33+grp*16+e]*PSCALE;
      }
    }
  } }

__global__ void k_psoftmax(){
  int p=blockIdx.x,b=blockIdx.y,t=threadIdx.x;
  float v=-1e30f;
  if(t<PP){ v=0.f;
    #pragma unroll
    for(int ks=0;ks<4;ks++) v+=g_attp4[((size_t)(ks*BB+b)*PP+p)*PP+t]; }
  __shared__ float sh[256];
  sh[t]=v; __syncthreads();
  for(int o=128;o;o>>=1){ if(t<o) sh[t]=fmaxf(sh[t],sh[t+o]); __syncthreads(); }
  float m=sh[0]; __syncthreads();
  float e=(t<PP)?__expf(v-m):0.f;
  sh[t]=e; __syncthreads();
  for(int o=128;o;o>>=1){ if(t<o) sh[t]+=sh[t+o]; __syncthreads(); }
  float inv=1.f/sh[0];
  if(t<PP) g_attpb[((size_t)b*PP+p)*PP+t]=__float2bfloat16(e*inv); }

__global__ void __launch_bounds__(256) k_ph_mm(){
  GEMM_PRE
  int b=blockIdx.z,m0=blockIdx.y*128,n0=blockIdx.x*128;
  const bf16* V=g_v+(size_t)b*HW*CCH;
  const bf16* A=g_attpb+(size_t)b*PP*PP;
  cp8(ABUF(0),V,PP,m0,16383,0,PP,t); cp8(BBUF(0),A,PP,n0,PP-1,0,PP,t); CPCOMMIT();
  for(int kt=0;kt<7;kt++){
    if(kt<6){ cp8(ABUF((kt+1)&1),V,PP,m0,16383,(kt+1)*32,PP,t);
              cp8(BBUF((kt+1)&1),A,PP,n0,PP-1,(kt+1)*32,PP,t); CPCOMMIT(); CPWAIT1(); }
    else CPWAIT0();
    __syncthreads();
    mma_tile(c,ABUF(kt&1),BBUF(kt&1),w,lane);
    __syncthreads();
  }
  int d=m0+m_;
  bf16* dst=g_hp+(size_t)b*HW*CCH+(size_t)d*PP;
  for(int j=0;j<4;j++){
    __syncthreads(); dump_chunk(Cs,w,lane,j,c); __syncthreads();
    #pragma unroll
    for(int e=0;e<16;e++){
      int p=n0+j*32+grp*16+e;
      if(p<PP) dst[p]=__float2bfloat16(Cs[m_*33+grp*16+e]);
    }
  } }

__global__ void k_pool_qk(){
  int a=blockIdx.x,b=blockIdx.y,c=threadIdx.x,y=a/TG,x=a%TG;
  size_t h00=(size_t)(2*y*112+2*x)*CCH+c;
  const bf16* Q=g_qT+(size_t)b*HW*CCH;
  const bf16* K=g_kT+(size_t)b*HW*CCH;
  float qv=0.25f*(__bfloat162float(Q[h00])+__bfloat162float(Q[h00+CCH])+__bfloat162float(Q[h00+112*CCH])+__bfloat162float(Q[h00+113*CCH]));
  float kv=0.25f*(__bfloat162float(K[h00])+__bfloat162float(K[h00+CCH])+__bfloat162float(K[h00+112*CCH])+__bfloat162float(K[h00+113*CCH]));
  g_qpT[((size_t)b*AA+a)*CCH+c]=__float2bfloat16(qv);
  g_kpT[((size_t)b*AA+a)*CCH+c]=__float2bfloat16(kv); }
__global__ void k_pool_v(){
  int c=blockIdx.x,b=blockIdx.y,t=threadIdx.x;
  const bf16* V=g_v+(size_t)b*HW*CCH+(size_t)c*HW;
  bf16* dst=g_vp+((size_t)b*CCH+c)*AA;
  for(int i=0;i<13;i++){
    int a=t+i*256;
    if(a<AA){
      int y=a/TG,x=a%TG,h00=2*y*112+2*x;
      float v=0.25f*(__bfloat162float(V[h00])+__bfloat162float(V[h00+1])+__bfloat162float(V[h00+112])+__bfloat162float(V[h00+113]));
      dst[a]=__float2bfloat16(v);
    }
  } }

__global__ void __launch_bounds__(256) k_gscore_mm(){
  GEMM_PRE
  int b=blockIdx.z,m0=blockIdx.y*128,n0=blockIdx.x*128;
  const bf16* Q=g_qpT+(size_t)b*AA*CCH;
  const bf16* K=g_kpT+(size_t)b*AA*CCH;
  cp16(ABUF(0),Q,CCH,m0,AA-1,t); cp16(BBUF(0),K,CCH,n0,AA-1,t); CPCOMMIT();
  for(int kt=0;kt<8;kt++){
    if(kt<7){ cp16(ABUF((kt+1)&1),Q+(kt+1)*32,CCH,m0,AA-1,t);
              cp16(BBUF((kt+1)&1),K+(kt+1)*32,CCH,n0,AA-1,t); CPCOMMIT(); CPWAIT1(); }
    else CPWAIT0();
    __syncthreads();
    mma_tile(c,ABUF(kt&1),BBUF(kt&1),w,lane);
    __syncthreads();
  }
  int p=m0+m_;
  float* dst=g_attg+((size_t)b*AA+(p<AA?p:0))*AA;
  for(int j=0;j<4;j++){
    __syncthreads(); dump_chunk(Cs,w,lane,j,c); __syncthreads();
    if(p<AA){
      #pragma unroll
      for(int e=0;e<16;e++){
        int q=n0+j*32+grp*16+e;
        if(q<AA) dst[q]=Cs[m_*33+grp*16+e]*GSCALE;
      }
    }
  } }

__global__ void k_gsoftmax(){
  size_t row=(size_t)blockIdx.y*AA+blockIdx.x;
  const float* src=g_attg+row*AA;
  bf16* dst=g_attgb+row*AA;
  int t=threadIdx.x;
  float v[13],mx=-1e30f;
  #pragma unroll
  for(int i=0;i<13;i++){ int c=t+i*256; v[i]=(c<AA)?src[c]:-1e30f; mx=fmaxf(mx,v[i]); }
  __shared__ float sh[256];
  sh[t]=mx; __syncthreads();
  for(int o=128;o;o>>=1){ if(t<o) sh[t]=fmaxf(sh[t],sh[t+o]); __syncthreads(); }
  float m=sh[0]; __syncthreads();
  float s=0.f;
  #pragma unroll
  for(int i=0;i<13;i++){ int c=t+i*256; if(c<AA){ v[i]=__expf(v[i]-m); s+=v[i]; } }
  sh[t]=s; __syncthreads();
  for(int o=128;o;o>>=1){ if(t<o) sh[t]+=sh[t+o]; __syncthreads(); }
  float inv=1.f/sh[0];
  #pragma unroll
  for(int i=0;i<13;i++){ int c=t+i*256; if(c<AA) dst[c]=__float2bfloat16(v[i]*inv); } }

__global__ void __launch_bounds__(256) k_gh_mm(){
  GEMM_PRE
  int b=blockIdx.z,m0=blockIdx.y*128,n0=blockIdx.x*128;
  const bf16* V=g_vp+(size_t)b*CCH*AA;
  const bf16* A=g_attgb+(size_t)b*AA*AA;
  cp16(ABUF(0),V,AA,m0,CCH-1,t); cp16(BBUF(0),A,AA,n0,AA-1,t); CPCOMMIT();
  for(int kt=0;kt<98;kt++){
    if(kt<97){ cp16(ABUF((kt+1)&1),V+(kt+1)*32,AA,m0,CCH-1,t);
               cp16(BBUF((kt+1)&1),A+(kt+1)*32,AA,n0,AA-1,t); CPCOMMIT(); CPWAIT1(); }
    else CPWAIT0();
    __syncthreads();
    mma_tile(c,ABUF(kt&1),BBUF(kt&1),w,lane);
    __syncthreads();
  }
  int cc=m0+m_;
  float* dst=g_hg+((size_t)b*CCH+cc)*AA;
  for(int j=0;j<4;j++){
    __syncthreads(); dump_chunk(Cs,w,lane,j,c); __syncthreads();
    #pragma unroll
    for(int e=0;e<16;e++){
      int a=n0+j*32+grp*16+e;
      if(a<AA) dst[a]=Cs[m_*33+grp*16+e];
    }
  } }

__global__ void __launch_bounds__(256) k_comb(){
  __shared__ bf16 sm[32][132];
  int b=blockIdx.z,c0=blockIdx.y*32,hw0=blockIdx.x*128,t=threadIdx.x;
  #pragma unroll
  for(int i=0;i<4;i++){
    int r=i*8+(t>>5),ch=t&31,c=c0+r;
    const bf16* hp=g_hp+(size_t)b*HW*CCH+(size_t)c*HW+hw0+ch*4;
    const float* hg=g_hg+((size_t)b*CCH+c)*AA;
    uint2 raw=*(const uint2*)hp; bf16 hpv[4]; *(uint2*)hpv=raw;
    #pragma unroll
    for(int e=0;e<4;e++){
      int hw=hw0+ch*4+e,yi=hw/112,xj=hw%112;
      float sy=yi*0.5f-0.25f; int y0=(int)floorf(sy); float fy=sy-(float)y0;
      int y0c=max(y0,0),y1c=min(y0+1,TG-1);
      float sx=xj*0.5f-0.25f; int x0=(int)floorf(sx); float fx=sx-(float)x0;
      int x0c=max(x0,0),x1c=min(x0+1,TG-1);
      float hv=(1.f-fy)*((1.f-fx)*hg[y0c*TG+x0c]+fx*hg[y0c*TG+x1c])+fy*((1.f-fx)*hg[y1c*TG+x0c]+fx*hg[y1c*TG+x1c]);
      sm[r][ch*4+e]=__float2bfloat16(0.75f*__bfloat162float(hpv[e])+0.25f*hv);
    }
  }
  __syncthreads();
  bf16* dst=g_hT+(size_t)b*HW*CCH;
  #pragma unroll
  for(int i=0;i<2;i++){
    int sl=t+i*256,j=sl>>2,part=sl&3; unsigned short tmp[8];
    #pragma unroll
    for(int e=0;e<8;e++) tmp[e]=*(unsigned short*)&sm[part*8+e][j];
    *(uint4*)(dst+(size_t)(hw0+j)*CCH+c0+part*8)=*(uint4*)tmp;
  } }

__global__ void __launch_bounds__(256) k_proj_mm(const float* __restrict__ x,float* __restrict__ out){
  GEMM_PRE
  int b=blockIdx.z,o0=blockIdx.y*128,n0=blockIdx.x*128;
  const bf16* W=g_wb+(size_t)3*65536;
  const bf16* Hh=g_hT+(size_t)b*HW*CCH;
  cp16(ABUF(0),W,CCH,o0,255,t); cp16(BBUF(0),Hh,CCH,n0,HW-1,t); CPCOMMIT();
  for(int kt=0;kt<8;kt++){
    if(kt<7){ cp16(ABUF((kt+1)&1),W+(kt+1)*32,CCH,o0,255,t);
              cp16(BBUF((kt+1)&1),Hh+(kt+1)*32,CCH,n0,HW-1,t); CPCOMMIT(); CPWAIT1(); }
    else CPWAIT0();
    __syncthreads();
    mma_tile(c,ABUF(kt&1),BBUF(kt&1),w,lane);
    __syncthreads();
  }
  int o=o0+m_;
  size_t base=(size_t)b*CHW+(size_t)o*HW;
  for(int j=0;j<4;j++){
    __syncthreads(); dump_chunk(Cs,w,lane,j,c); __syncthreads();
    #pragma unroll
    for(int e=0;e<16;e++){
      size_t off=base+n0+j*32+grp*16+e;
      out[off]=Cs[m_*33+grp*16+e]+x[off];
    }
  } }

extern "C" void kernel_launch(void* const* d_in,const int* in_sizes,int n_in,void* d_out,int out_size){
  const float* x =(const float*)d_in[0];
  const float* gw=(const float*)d_in[1];
  const float* gb=(const float*)d_in[2];
  const float* wq=(const float*)d_in[3];
  const float* bq=(const float*)d_in[4];
  const float* wk=(const float*)d_in[5];
  const float* bk=(const float*)d_in[6];
  const float* wv=(const float*)d_in[7];
  const float* bv=(const float*)d_in[8];
  const float* wp=(const float*)d_in[9];
  float* out=(float*)d_out;
  k_zero<<<1,32>>>();
  k_wcvt<<<256,256>>>(wq,wk,wv,wp);
  k_gnstats<<<dim3(64,8),256>>>(x);
  k_gnfin<<<1,32>>>();
  k_normT<<<dim3(98,8,8),256>>>(x,gw,gb);
  k_qkv_mm<<<dim3(98,6,8),256>>>(bq,bk,bv);
  k_pscore_mm<<<dim3(2,2,32),256>>>();
  k_psoftmax<<<dim3(PP,BB),256>>>();
  k_ph_mm<<<dim3(2,128,8),256>>>();
  k_pool_qk<<<dim3(AA,BB),256>>>();
  k_pool_v<<<dim3(CCH,BB),256>>>();
  k_gscore_mm<<<dim3(25,25,8),256>>>();
  k_gsoftmax<<<dim3(AA,BB),256>>>();
  k_gh_mm<<<dim3(25,2,8),256>>>();
  k_comb<<<dim3(98,8,8),256>>>();
  k_proj_mm<<<dim3(98,2,8),256>>>(x,out);
}